// round 11
// baseline (speedup 1.0000x reference)
#include <cuda_runtime.h>
#include <cstdint>

// KVCacheManager update_cache, token-gen path.
//   L=2, B=4, H=8, M=4096, D=128, fp32
//   out shape: (2[kv], L, B, H, M, D)
//   out[kv,l,b,h,m,d] = (m == pos[b] && pos[b] < seq_len) ? latest[l,b,h,d]
//                                                         : cache[l,b,h,m,d]
//
// HBM-bound streaming copy with fused point-scatter.
// Measured floor: ~6.4-6.7 TB/s (~80% of 8TB/s) for a 1:1 read:write stream,
// invariant under cache hints (R3/R5), SM-vs-CE path (R4), and 128b-vs-256b
// width (R6). R7(final): v8.f32 accesses (lowest issue pressure, best kernel
// dur 75.42us) + 4-deep load-group / store-group per thread to lengthen
// per-warp directional bursts (4KB read then 4KB write).
//
// v8-chunk linear index (23 bits = 8,388,608 chunks of 8 floats):
//   d8 : bits [0:4)   (16 v8-chunks per D=128 row)
//   m  : bits [4:16)  (4096)
//   h  : bits [16:19) (8)
//   b  : bits [19:21) (4)
//   l  : bit  [21]    (2)
//   kv : bit  [22]    (2)

static constexpr unsigned TOTAL_V8  = 1u << 23;        // 8,388,608 chunks
static constexpr unsigned HALF_MASK = (1u << 22) - 1;  // within one cache
static constexpr unsigned THREADS   = 256;
static constexpr unsigned VPT       = 4;               // v8 chunks per thread
static constexpr unsigned GRID      = TOTAL_V8 / (THREADS * VPT); // 8192

struct __align__(32) f8 { float v[8]; };

__device__ __forceinline__ f8 ldg256(const f8* p)
{
    f8 r;
    asm volatile("ld.global.nc.v8.f32 {%0,%1,%2,%3,%4,%5,%6,%7}, [%8];"
                 : "=f"(r.v[0]), "=f"(r.v[1]), "=f"(r.v[2]), "=f"(r.v[3]),
                   "=f"(r.v[4]), "=f"(r.v[5]), "=f"(r.v[6]), "=f"(r.v[7])
                 : "l"(p));
    return r;
}

__device__ __forceinline__ void stg256(f8* p, const f8& r)
{
    asm volatile("st.global.v8.f32 [%0], {%1,%2,%3,%4,%5,%6,%7,%8};"
                 :: "l"(p),
                    "f"(r.v[0]), "f"(r.v[1]), "f"(r.v[2]), "f"(r.v[3]),
                    "f"(r.v[4]), "f"(r.v[5]), "f"(r.v[6]), "f"(r.v[7])
                 : "memory");
}

__device__ __forceinline__ f8 load_elem(
    unsigned j,
    const f8* __restrict__ k_cache,
    const f8* __restrict__ v_cache,
    const f8* __restrict__ latest_k,
    const f8* __restrict__ latest_v,
    const int* __restrict__ pos, int S)
{
    unsigned d8 = j & 15u;
    unsigned m  = (j >> 4)  & 4095u;
    unsigned h  = (j >> 16) & 7u;
    unsigned b  = (j >> 19) & 3u;
    unsigned l  = (j >> 21) & 1u;
    unsigned kv = (j >> 22) & 1u;
    unsigned ci = j & HALF_MASK;

    int p = __ldg(&pos[b]);
    if ((int)m == p && p < S) {
        // latest_{k,v}: (L,B,H,1,D) -> v8 index ((l*B+b)*H+h)*16 + d8
        unsigned li = ((((l << 2) + b) << 3) + h) * 16u + d8;
        return kv ? ldg256(&latest_v[li]) : ldg256(&latest_k[li]);
    }
    return kv ? ldg256(&v_cache[ci]) : ldg256(&k_cache[ci]);
}

__global__ void __launch_bounds__(THREADS)
kv_update_kernel(const f8* __restrict__ k_cache,
                 const f8* __restrict__ v_cache,
                 const f8* __restrict__ latest_k,
                 const f8* __restrict__ latest_v,
                 const int* __restrict__ pos,
                 const int* __restrict__ seq_len_p,
                 f8*        __restrict__ out)
{
    const unsigned span = GRID * THREADS;   // 2,097,152
    unsigned j0 = blockIdx.x * THREADS + threadIdx.x;

    int S = seq_len_p ? __ldg(seq_len_p) : 4096;

    // 4 independent 256-bit loads (4KB/warp read burst), then 4 grouped
    // 256-bit stores (4KB/warp write burst).
    f8 r[VPT];
#pragma unroll
    for (unsigned k = 0; k < VPT; k++)
        r[k] = load_elem(j0 + k * span,
                         k_cache, v_cache, latest_k, latest_v, pos, S);
#pragma unroll
    for (unsigned k = 0; k < VPT; k++)
        stg256(&out[j0 + k * span], r[k]);
}

extern "C" void kernel_launch(void* const* d_in, const int* in_sizes, int n_in,
                              void* d_out, int out_size)
{
    // metadata order: k_caches, v_caches, latest_k, latest_v, position_ids, seq_len
    const f8* k_cache  = (const f8*)d_in[0];
    const f8* v_cache  = (const f8*)d_in[1];
    const f8* latest_k = (const f8*)d_in[2];
    const f8* latest_v = (const f8*)d_in[3];
    const int* pos     = (const int*)d_in[4];
    const int* seq_len = (n_in >= 6) ? (const int*)d_in[5] : nullptr;
    f8* out = (f8*)d_out;

    kv_update_kernel<<<GRID, THREADS>>>(k_cache, v_cache, latest_k, latest_v,
                                        pos, seq_len, out);
    (void)in_sizes; (void)out_size;
}

// round 12
// speedup vs baseline: 1.0035x; 1.0035x over previous
#include <cuda_runtime.h>
#include <cstdint>

// KVCacheManager update_cache, token-gen path.
//   L=2, B=4, H=8, M=4096, D=128, fp32
//   out shape: (2[kv], L, B, H, M, D)
//   out[kv,l,b,h,m,d] = (m == pos[b] && pos[b] < seq_len) ? latest[l,b,h,d]
//                                                         : cache[l,b,h,m,d]
//
// HBM-bound streaming copy with fused point-scatter — FINAL (R6 config).
//
// Session findings: ~6.4 TB/s (~80% of 8 TB/s spec) is the GB300 floor for a
// 1:1 read:write stream, invariant under cache hints (R3/R5), SM-vs-CE path
// (R4), 128b-vs-256b width (R6), MLP depth / burst grouping (R2/R3/R7), and
// layout. Best config: v8.f32 accesses, 2 chunks/thread grid-span strided,
// 26 regs -> ~78% occupancy. Kernel 75.4us, harness ~81us.
//
// v8-chunk linear index (23 bits = 8,388,608 chunks of 8 floats):
//   d8 : bits [0:4)   (16 v8-chunks per D=128 row)
//   m  : bits [4:16)  (4096)
//   h  : bits [16:19) (8)
//   b  : bits [19:21) (4)
//   l  : bit  [21]    (2)
//   kv : bit  [22]    (2)
// Scatter branch is half-warp-uniform (v8 spans 16 lanes/row) -> ~2 divergent
// warps chip-wide, negligible.

static constexpr unsigned TOTAL_V8  = 1u << 23;        // 8,388,608 chunks
static constexpr unsigned HALF_MASK = (1u << 22) - 1;  // within one cache
static constexpr unsigned THREADS   = 256;
static constexpr unsigned VPT       = 2;               // v8 chunks per thread
static constexpr unsigned GRID      = TOTAL_V8 / (THREADS * VPT); // 16384

struct __align__(32) f8 { float v[8]; };

__device__ __forceinline__ f8 ldg256(const f8* p)
{
    f8 r;
    asm volatile("ld.global.nc.v8.f32 {%0,%1,%2,%3,%4,%5,%6,%7}, [%8];"
                 : "=f"(r.v[0]), "=f"(r.v[1]), "=f"(r.v[2]), "=f"(r.v[3]),
                   "=f"(r.v[4]), "=f"(r.v[5]), "=f"(r.v[6]), "=f"(r.v[7])
                 : "l"(p));
    return r;
}

__device__ __forceinline__ void stg256(f8* p, const f8& r)
{
    asm volatile("st.global.v8.f32 [%0], {%1,%2,%3,%4,%5,%6,%7,%8};"
                 :: "l"(p),
                    "f"(r.v[0]), "f"(r.v[1]), "f"(r.v[2]), "f"(r.v[3]),
                    "f"(r.v[4]), "f"(r.v[5]), "f"(r.v[6]), "f"(r.v[7])
                 : "memory");
}

__device__ __forceinline__ f8 load_elem(
    unsigned j,
    const f8* __restrict__ k_cache,
    const f8* __restrict__ v_cache,
    const f8* __restrict__ latest_k,
    const f8* __restrict__ latest_v,
    const int* __restrict__ pos, int S)
{
    unsigned d8 = j & 15u;
    unsigned m  = (j >> 4)  & 4095u;
    unsigned h  = (j >> 16) & 7u;
    unsigned b  = (j >> 19) & 3u;
    unsigned l  = (j >> 21) & 1u;
    unsigned kv = (j >> 22) & 1u;
    unsigned ci = j & HALF_MASK;

    int p = __ldg(&pos[b]);
    if ((int)m == p && p < S) {
        // latest_{k,v}: (L,B,H,1,D) -> v8 index ((l*B+b)*H+h)*16 + d8
        unsigned li = ((((l << 2) + b) << 3) + h) * 16u + d8;
        return kv ? ldg256(&latest_v[li]) : ldg256(&latest_k[li]);
    }
    return kv ? ldg256(&v_cache[ci]) : ldg256(&k_cache[ci]);
}

__global__ void __launch_bounds__(THREADS)
kv_update_kernel(const f8* __restrict__ k_cache,
                 const f8* __restrict__ v_cache,
                 const f8* __restrict__ latest_k,
                 const f8* __restrict__ latest_v,
                 const int* __restrict__ pos,
                 const int* __restrict__ seq_len_p,
                 f8*        __restrict__ out)
{
    const unsigned span = GRID * THREADS;   // 4,194,304
    unsigned j0 = blockIdx.x * THREADS + threadIdx.x;
    unsigned j1 = j0 + span;

    int S = seq_len_p ? __ldg(seq_len_p) : 4096;

    // Two independent 256-bit load chains, fully coalesced.
    f8 v0 = load_elem(j0, k_cache, v_cache, latest_k, latest_v, pos, S);
    f8 v1 = load_elem(j1, k_cache, v_cache, latest_k, latest_v, pos, S);
    stg256(&out[j0], v0);
    stg256(&out[j1], v1);
}

extern "C" void kernel_launch(void* const* d_in, const int* in_sizes, int n_in,
                              void* d_out, int out_size)
{
    // metadata order: k_caches, v_caches, latest_k, latest_v, position_ids, seq_len
    const f8* k_cache  = (const f8*)d_in[0];
    const f8* v_cache  = (const f8*)d_in[1];
    const f8* latest_k = (const f8*)d_in[2];
    const f8* latest_v = (const f8*)d_in[3];
    const int* pos     = (const int*)d_in[4];
    const int* seq_len = (n_in >= 6) ? (const int*)d_in[5] : nullptr;
    f8* out = (f8*)d_out;

    kv_update_kernel<<<GRID, THREADS>>>(k_cache, v_cache, latest_k, latest_v,
                                        pos, seq_len, out);
    (void)in_sizes; (void)out_size;
}

// round 13
// speedup vs baseline: 1.0090x; 1.0055x over previous
#include <cuda_runtime.h>
#include <cstdint>

// KVCacheManager update_cache, token-gen path — FINAL (best-measured config, R2).
//   L=2, B=4, H=8, M=4096, D=128, fp32
//   out shape: (2[kv], L, B, H, M, D)
//   out[kv,l,b,h,m,d] = (m == pos[b] && pos[b] < seq_len) ? latest[l,b,h,d]
//                                                         : cache[l,b,h,m,d]
//
// HBM-bound streaming copy with fused point-scatter. float4-vectorized.
//
// Session findings (R2-R12): ~6.4 TB/s (~80% of 8 TB/s spec) is the GB300
// floor for a 1:1 read:write stream — invariant under cache hints (R3/R5),
// SM-vs-CE path (R4), 128b-vs-256b access width (R6), MLP depth / burst
// grouping (R7), and layout. All coalesced variants with occ>=76% measure
// 75.4-76.1us kernel. This config had the best harness measurement (81.1us)
// and tied-best DRAM% (80.7) with the simplest code (20 regs, occ 79.6%).
//
// Linear float4 index bit layout (24 bits = 16,777,216 float4s):
//   d4 : bits [0:5)   (32 float4 per D=128 row)
//   m  : bits [5:17)  (4096)
//   h  : bits [17:20) (8)
//   b  : bits [20:22) (4)
//   l  : bit  [22]    (2)
//   kv : bit  [23]    (2)
// Within a warp all lanes share m,b -> scatter branch is warp-uniform.

static constexpr unsigned TOTAL_VEC4 = 1u << 24;       // 16,777,216 float4s
static constexpr unsigned HALF_MASK  = (1u << 23) - 1; // index within one cache
static constexpr unsigned THREADS    = 256;
static constexpr unsigned VEC_PER_THREAD = 2;          // independent loads (MLP)
static constexpr unsigned GRID = TOTAL_VEC4 / (THREADS * VEC_PER_THREAD); // 32768

__device__ __forceinline__ float4 load_elem(
    unsigned i,
    const float4* __restrict__ k_cache,
    const float4* __restrict__ v_cache,
    const float4* __restrict__ latest_k,
    const float4* __restrict__ latest_v,
    const int* __restrict__ pos, int S)
{
    unsigned d4 = i & 31u;
    unsigned m  = (i >> 5)  & 4095u;
    unsigned h  = (i >> 17) & 7u;
    unsigned b  = (i >> 20) & 3u;
    unsigned l  = (i >> 22) & 1u;
    unsigned kv = (i >> 23) & 1u;
    unsigned ci = i & HALF_MASK;

    int p = __ldg(&pos[b]);
    if ((int)m == p && p < S) {
        // latest_{k,v}: (L,B,H,1,D) -> float4 index ((l*B+b)*H+h)*32 + d4
        unsigned li = ((((l << 2) + b) << 3) + h) * 32u + d4;
        return kv ? __ldg(&latest_v[li]) : __ldg(&latest_k[li]);
    }
    return kv ? __ldg(&v_cache[ci]) : __ldg(&k_cache[ci]);
}

__global__ void __launch_bounds__(THREADS)
kv_update_kernel(const float4* __restrict__ k_cache,
                 const float4* __restrict__ v_cache,
                 const float4* __restrict__ latest_k,
                 const float4* __restrict__ latest_v,
                 const int*    __restrict__ pos,
                 const int*    __restrict__ seq_len_p,
                 float4*       __restrict__ out)
{
    const unsigned span = GRID * THREADS;   // 8,388,608
    unsigned i0 = blockIdx.x * THREADS + threadIdx.x;
    unsigned i1 = i0 + span;

    int S = seq_len_p ? __ldg(seq_len_p) : 4096;

    // Two independent load chains -> MLP=2 per thread, fully coalesced.
    float4 v0 = load_elem(i0, k_cache, v_cache, latest_k, latest_v, pos, S);
    float4 v1 = load_elem(i1, k_cache, v_cache, latest_k, latest_v, pos, S);
    out[i0] = v0;
    out[i1] = v1;
}

extern "C" void kernel_launch(void* const* d_in, const int* in_sizes, int n_in,
                              void* d_out, int out_size)
{
    // metadata order: k_caches, v_caches, latest_k, latest_v, position_ids, seq_len
    const float4* k_cache  = (const float4*)d_in[0];
    const float4* v_cache  = (const float4*)d_in[1];
    const float4* latest_k = (const float4*)d_in[2];
    const float4* latest_v = (const float4*)d_in[3];
    const int*    pos      = (const int*)d_in[4];
    const int*    seq_len  = (n_in >= 6) ? (const int*)d_in[5] : nullptr;
    float4*       out      = (float4*)d_out;

    kv_update_kernel<<<GRID, THREADS>>>(k_cache, v_cache, latest_k, latest_v,
                                        pos, seq_len, out);
    (void)in_sizes; (void)out_size;
}

// round 14
// speedup vs baseline: 1.0278x; 1.0187x over previous
#include <cuda_runtime.h>
#include <cstdint>

// KVCacheManager update_cache, token-gen path.
//   L=2, B=4, H=8, M=4096, D=128, fp32
//   out shape: (2[kv], L, B, H, M, D)
//   out[kv,l,b,h,m,d] = (m == pos[b] && pos[b] < seq_len) ? latest[l,b,h,d]
//                                                         : cache[l,b,h,m,d]
//
// HBM-bound streaming copy with fused point-scatter. float4-vectorized.
//
// Session findings (R2-R13): ~6.4-6.45 TB/s (~80-81% of 8 TB/s spec) is the
// GB300 floor for a 1:1 read:write stream — invariant under cache hints,
// SM-vs-CE path, 128b/256b width, MLP depth, and layout. Best config: float4,
// VPT=2 grid-span strided, 20 regs (kernel 74.9us, DRAM 81.5%).
//
// R14: final unswept knob — block size 256 -> 512 (same total threads, same
// instruction stream). Halves CTAs/SM -> less cross-CTA L1tex queue
// contention per the B300 multi-CTA spread model. Expected |delta| <= 1%.
//
// Linear float4 index bit layout (24 bits = 16,777,216 float4s):
//   d4 : bits [0:5)   (32 float4 per D=128 row)
//   m  : bits [5:17)  (4096)
//   h  : bits [17:20) (8)
//   b  : bits [20:22) (4)
//   l  : bit  [22]    (2)
//   kv : bit  [23]    (2)
// Within a warp all lanes share m,b -> scatter branch is warp-uniform.

static constexpr unsigned TOTAL_VEC4 = 1u << 24;       // 16,777,216 float4s
static constexpr unsigned HALF_MASK  = (1u << 23) - 1; // index within one cache
static constexpr unsigned THREADS    = 512;
static constexpr unsigned VEC_PER_THREAD = 2;          // independent loads (MLP)
static constexpr unsigned GRID = TOTAL_VEC4 / (THREADS * VEC_PER_THREAD); // 16384

__device__ __forceinline__ float4 load_elem(
    unsigned i,
    const float4* __restrict__ k_cache,
    const float4* __restrict__ v_cache,
    const float4* __restrict__ latest_k,
    const float4* __restrict__ latest_v,
    const int* __restrict__ pos, int S)
{
    unsigned d4 = i & 31u;
    unsigned m  = (i >> 5)  & 4095u;
    unsigned h  = (i >> 17) & 7u;
    unsigned b  = (i >> 20) & 3u;
    unsigned l  = (i >> 22) & 1u;
    unsigned kv = (i >> 23) & 1u;
    unsigned ci = i & HALF_MASK;

    int p = __ldg(&pos[b]);
    if ((int)m == p && p < S) {
        // latest_{k,v}: (L,B,H,1,D) -> float4 index ((l*B+b)*H+h)*32 + d4
        unsigned li = ((((l << 2) + b) << 3) + h) * 32u + d4;
        return kv ? __ldg(&latest_v[li]) : __ldg(&latest_k[li]);
    }
    return kv ? __ldg(&v_cache[ci]) : __ldg(&k_cache[ci]);
}

__global__ void __launch_bounds__(THREADS)
kv_update_kernel(const float4* __restrict__ k_cache,
                 const float4* __restrict__ v_cache,
                 const float4* __restrict__ latest_k,
                 const float4* __restrict__ latest_v,
                 const int*    __restrict__ pos,
                 const int*    __restrict__ seq_len_p,
                 float4*       __restrict__ out)
{
    const unsigned span = GRID * THREADS;   // 8,388,608
    unsigned i0 = blockIdx.x * THREADS + threadIdx.x;
    unsigned i1 = i0 + span;

    int S = seq_len_p ? __ldg(seq_len_p) : 4096;

    // Two independent load chains -> MLP=2 per thread, fully coalesced.
    float4 v0 = load_elem(i0, k_cache, v_cache, latest_k, latest_v, pos, S);
    float4 v1 = load_elem(i1, k_cache, v_cache, latest_k, latest_v, pos, S);
    out[i0] = v0;
    out[i1] = v1;
}

extern "C" void kernel_launch(void* const* d_in, const int* in_sizes, int n_in,
                              void* d_out, int out_size)
{
    // metadata order: k_caches, v_caches, latest_k, latest_v, position_ids, seq_len
    const float4* k_cache  = (const float4*)d_in[0];
    const float4* v_cache  = (const float4*)d_in[1];
    const float4* latest_k = (const float4*)d_in[2];
    const float4* latest_v = (const float4*)d_in[3];
    const int*    pos      = (const int*)d_in[4];
    const int*    seq_len  = (n_in >= 6) ? (const int*)d_in[5] : nullptr;
    float4*       out      = (float4*)d_out;

    kv_update_kernel<<<GRID, THREADS>>>(k_cache, v_cache, latest_k, latest_v,
                                        pos, seq_len, out);
    (void)in_sizes; (void)out_size;
}